// round 12
// baseline (speedup 1.0000x reference)
#include <cuda_runtime.h>
#include <cuda_fp16.h>
#include <cstdint>

#define NS 4096
#define NA 1024
#define ND 5
#define NH 64
#define TILES 4
#define PADK 72          // f16 elems per row (144B): ldmatrix bank-conflict-free

struct Smem {
    __half   w2hi[NH][PADK];     // B^T: [j_out][k_in], f16 hi (layer-2 residual dropped)
    uint32_t w1ph[4][72];        // W1ext pairs (k,k+1) as f16x2: [kpair][j]
    uint32_t w1pl[4][72];        // layer-1 keeps full 3-term split
    float    b2[NH], w3[NH];
};

__device__ __forceinline__ uint32_t smem_u32(const void* p) {
    uint32_t a;
    asm("{ .reg .u64 t; cvta.to.shared.u64 t, %1; cvt.u32.u64 %0, t; }" : "=r"(a) : "l"(p));
    return a;
}
__device__ __forceinline__ void ldsm_x4(uint32_t r[4], uint32_t addr) {
    asm volatile("ldmatrix.sync.aligned.m8n8.x4.shared.b16 {%0,%1,%2,%3}, [%4];"
                 : "=r"(r[0]), "=r"(r[1]), "=r"(r[2]), "=r"(r[3]) : "r"(addr));
}
__device__ __forceinline__ void mma16816(float c[4], const uint32_t a[4], const uint32_t b[2]) {
    asm volatile("mma.sync.aligned.m16n8k16.row.col.f32.f16.f16.f32 "
                 "{%0,%1,%2,%3}, {%4,%5,%6,%7}, {%8,%9}, {%0,%1,%2,%3};"
                 : "+f"(c[0]), "+f"(c[1]), "+f"(c[2]), "+f"(c[3])
                 : "r"(a[0]), "r"(a[1]), "r"(a[2]), "r"(a[3]), "r"(b[0]), "r"(b[1]));
}
__device__ __forceinline__ void mma16816_z(float c[4], const uint32_t a[4], const uint32_t b[2]) {
    asm volatile("mma.sync.aligned.m16n8k16.row.col.f32.f16.f16.f32 "
                 "{%0,%1,%2,%3}, {%4,%5,%6,%7}, {%8,%9}, {%10,%10,%10,%10};"
                 : "=f"(c[0]), "=f"(c[1]), "=f"(c[2]), "=f"(c[3])
                 : "r"(a[0]), "r"(a[1]), "r"(a[2]), "r"(a[3]), "r"(b[0]), "r"(b[1]),
                   "f"(0.0f));
}
__device__ __forceinline__ void mma16808(float c[4], uint32_t a0, uint32_t a1, uint32_t b0) {
    asm volatile("mma.sync.aligned.m16n8k8.row.col.f32.f16.f16.f32 "
                 "{%0,%1,%2,%3}, {%4,%5}, {%6}, {%0,%1,%2,%3};"
                 : "+f"(c[0]), "+f"(c[1]), "+f"(c[2]), "+f"(c[3])
                 : "r"(a0), "r"(a1), "r"(b0));
}
__device__ __forceinline__ void mma16808_z(float c[4], uint32_t a0, uint32_t a1, uint32_t b0) {
    asm volatile("mma.sync.aligned.m16n8k8.row.col.f32.f16.f16.f32 "
                 "{%0,%1,%2,%3}, {%4,%5}, {%6}, {%7,%7,%7,%7};"
                 : "=f"(c[0]), "=f"(c[1]), "=f"(c[2]), "=f"(c[3])
                 : "r"(a0), "r"(a1), "r"(b0), "f"(0.0f));
}

// HW tanh: single MUFU.TANH (PTX tanh.approx.f32, baseline sm_75+).
__device__ __forceinline__ float fast_tanh(float x) {
    float y;
    asm("tanh.approx.f32 %0, %1;" : "=f"(y) : "f"(x));
    return y;
}
__device__ __forceinline__ uint32_t h2u(__half2 h) { return *reinterpret_cast<uint32_t*>(&h); }

__device__ __forceinline__ void split2(float x, float y, uint32_t& hi, uint32_t& lo) {
    __half2 h = __floats2half2_rn(x, y);
    float2  f = __half22float2(h);
    hi = h2u(h);
    lo = h2u(__floats2half2_rn(x - f.x, y - f.y));
}

__global__ void __launch_bounds__(128, 3) mlp_hmma5_kernel(
    const float* __restrict__ g,
    const float* __restrict__ W1, const float* __restrict__ b1,
    const float* __restrict__ W2, const float* __restrict__ b2,
    const float* __restrict__ W3, const float* __restrict__ b3,
    float* __restrict__ out)
{
    extern __shared__ __align__(16) char smem_raw[];
    Smem* sm = reinterpret_cast<Smem*>(smem_raw);

    const int a    = blockIdx.x;
    const int tid  = threadIdx.x;
    const int w    = tid >> 5;
    const int lane = tid & 31;
    const int q    = lane & 3;
    const int r0   = lane >> 2;

    // ---- stage W2 (f16 hi only), transposed: B^T[j][k] ----
    for (int e = tid; e < NH * NH; e += 128) {
        int kin = e >> 6, j = e & 63;
        sm->w2hi[j][kin] = __float2half_rn(W2[(size_t)a * NH * NH + e]);
    }
    // ---- stage W1ext pairs: rows 0..4 = W1, row 5 = b1, rows 6,7 = 0 ----
    for (int e = tid; e < 256; e += 128) {
        int kp = e >> 6, j = e & 63;
        int k0 = 2 * kp, k1 = k0 + 1;
        float x = (k0 < ND) ? W1[(size_t)a * ND * NH + k0 * NH + j] : 0.0f;
        float y = (k1 < ND) ? W1[(size_t)a * ND * NH + k1 * NH + j]
                            : ((k1 == ND) ? b1[(size_t)a * NH + j] : 0.0f);
        uint32_t hi, lo;
        split2(x, y, hi, lo);
        sm->w1ph[kp][j] = hi;
        sm->w1pl[kp][j] = lo;
    }
    if (tid < NH) {
        sm->b2[tid] = b2[(size_t)a * NH + tid];
        sm->w3[tid] = W3[(size_t)a * NH + tid];
    }
    __syncthreads();

    const float bias3 = b3[a];
    // ldsm_x4 address: matrix mi = lane>>3; row = (lane&7) + 8*(mi>>1) [nt-pair row-block],
    // col-half = mi&1. Yields frags (nt,b0),(nt,b1),(nt+1,b0),(nt+1,b1).
    const uint32_t aB4 = smem_u32(&sm->w2hi[(lane & 7) + 8 * (lane >> 4)][0])
                       + ((lane >> 3) & 1) * 16;

    // ---- loop-invariant W1ext B-fragments ----
    uint32_t bw1h[8], bw1l[8];
#pragma unroll
    for (int nt = 0; nt < 8; nt++) {
        bw1h[nt] = sm->w1ph[q][nt * 8 + r0];
        bw1l[nt] = sm->w1pl[q][nt * 8 + r0];
    }

    const int swb0 = blockIdx.y * TILES * 128 + w * 32;
    const int d0   = 2 * q;

    // ---- g raw prefetch (tile 0) ----
    float grx[2][2], gry[2][2];
#pragma unroll
    for (int mt = 0; mt < 2; mt++)
#pragma unroll
        for (int rr = 0; rr < 2; rr++) {
            const size_t idx = ((size_t)(swb0 + mt * 16 + r0 + 8 * rr) * NA + a) * ND;
            grx[mt][rr] = (d0 < ND)     ? g[idx + d0]     : 0.0f;
            gry[mt][rr] = (d0 + 1 < ND) ? g[idx + d0 + 1] : 0.0f;
        }

#pragma unroll 1
    for (int t = 0; t < TILES; t++) {
        const int swb = swb0 + t * 128;

        // ---- build g A-fragments; d=5 slot carries 1.0 (bias row) ----
        uint32_t gh[2][2], gl[2][2];
#pragma unroll
        for (int mt = 0; mt < 2; mt++)
#pragma unroll
            for (int rr = 0; rr < 2; rr++) {
                float y = (d0 + 1 == ND) ? 1.0f : gry[mt][rr];
                split2(grx[mt][rr], y, gh[mt][rr], gl[mt][rr]);
            }

        // ---- prefetch next tile's g (overlaps the MMA phase) ----
        if (t + 1 < TILES) {
#pragma unroll
            for (int mt = 0; mt < 2; mt++)
#pragma unroll
                for (int rr = 0; rr < 2; rr++) {
                    const size_t idx =
                        ((size_t)(swb + 128 + mt * 16 + r0 + 8 * rr) * NA + a) * ND;
                    grx[mt][rr] = (d0 < ND)     ? g[idx + d0]     : 0.0f;
                    gry[mt][rr] = (d0 + 1 < ND) ? g[idx + d0 + 1] : 0.0f;
                }
        }

        float acc[2][8][4];
#pragma unroll
        for (int half = 0; half < 2; half++) {
            // ---- layer-1 MMA (3-term split) for nt = 4*half .. 4*half+3 ----
            float acc1[2][4][4];
#pragma unroll
            for (int ntl = 0; ntl < 4; ntl++) {
                const int nt = 4 * half + ntl;
#pragma unroll
                for (int mt = 0; mt < 2; mt++) {
                    mma16808_z(acc1[mt][ntl], gh[mt][0], gh[mt][1], bw1h[nt]);
                    mma16808 (acc1[mt][ntl], gl[mt][0], gl[mt][1], bw1h[nt]);
                    mma16808 (acc1[mt][ntl], gh[mt][0], gh[mt][1], bw1l[nt]);
                }
            }
            // ---- per k-chunk: tanh+split -> layer-2 (2-term: ah*bh + al*bh) ----
#pragma unroll
            for (int ksl = 0; ksl < 2; ksl++) {
                const int ks = 2 * half + ksl;
                uint32_t ah[2][4], al[2][4];
#pragma unroll
                for (int mt = 0; mt < 2; mt++) {
                    const float* e0 = acc1[mt][2 * ksl];
                    const float* e1 = acc1[mt][2 * ksl + 1];
                    split2(fast_tanh(e0[0]), fast_tanh(e0[1]), ah[mt][0], al[mt][0]);
                    split2(fast_tanh(e0[2]), fast_tanh(e0[3]), ah[mt][1], al[mt][1]);
                    split2(fast_tanh(e1[0]), fast_tanh(e1[1]), ah[mt][2], al[mt][2]);
                    split2(fast_tanh(e1[2]), fast_tanh(e1[3]), ah[mt][3], al[mt][3]);
                }
#pragma unroll
                for (int np = 0; np < 4; np++) {          // nt-pairs via one ldsm_x4
                    uint32_t b4[4];
                    ldsm_x4(b4, aB4 + np * 16 * (PADK * 2) + ks * 32);
#pragma unroll
                    for (int ntl = 0; ntl < 2; ntl++) {
                        const int nt = 2 * np + ntl;
                        const uint32_t* b2f = &b4[2 * ntl];
#pragma unroll
                        for (int mt = 0; mt < 2; mt++) {
                            if (ks == 0) mma16816_z(acc[mt][nt], ah[mt], b2f);
                            else         mma16816 (acc[mt][nt], ah[mt], b2f);
                            mma16816(acc[mt][nt], al[mt], b2f);
                        }
                    }
                }
            }
        }

        // ---- epilogue: +b2, tanh, dot(W3), quad-shuffle reduce, write 4 rows ----
        float p0 = 0.f, p1 = 0.f, p2 = 0.f, p3 = 0.f;
#pragma unroll
        for (int nt = 0; nt < 8; nt++) {
            float2 b2v = *(const float2*)&sm->b2[nt * 8 + q * 2];
            float2 w3v = *(const float2*)&sm->w3[nt * 8 + q * 2];
            p0 = fmaf(fast_tanh(acc[0][nt][0] + b2v.x), w3v.x, p0);
            p0 = fmaf(fast_tanh(acc[0][nt][1] + b2v.y), w3v.y, p0);
            p1 = fmaf(fast_tanh(acc[0][nt][2] + b2v.x), w3v.x, p1);
            p1 = fmaf(fast_tanh(acc[0][nt][3] + b2v.y), w3v.y, p1);
            p2 = fmaf(fast_tanh(acc[1][nt][0] + b2v.x), w3v.x, p2);
            p2 = fmaf(fast_tanh(acc[1][nt][1] + b2v.y), w3v.y, p2);
            p3 = fmaf(fast_tanh(acc[1][nt][2] + b2v.x), w3v.x, p3);
            p3 = fmaf(fast_tanh(acc[1][nt][3] + b2v.y), w3v.y, p3);
        }
#pragma unroll
        for (int d = 1; d <= 2; d <<= 1) {
            p0 += __shfl_xor_sync(0xFFFFFFFFu, p0, d);
            p1 += __shfl_xor_sync(0xFFFFFFFFu, p1, d);
            p2 += __shfl_xor_sync(0xFFFFFFFFu, p2, d);
            p3 += __shfl_xor_sync(0xFFFFFFFFu, p3, d);
        }
        if (q == 0) {
            const int rb = swb + r0;
            out[(size_t)(rb +  0) * NA + a] = p0 + bias3;
            out[(size_t)(rb +  8) * NA + a] = p1 + bias3;
            out[(size_t)(rb + 16) * NA + a] = p2 + bias3;
            out[(size_t)(rb + 24) * NA + a] = p3 + bias3;
        }
    }
}

extern "C" void kernel_launch(void* const* d_in, const int* in_sizes, int n_in,
                              void* d_out, int out_size) {
    const float* g  = (const float*)d_in[0];
    const float* W1 = (const float*)d_in[1];
    const float* b1 = (const float*)d_in[2];
    const float* W2 = (const float*)d_in[3];
    const float* b2 = (const float*)d_in[4];
    const float* W3 = (const float*)d_in[5];
    const float* b3 = (const float*)d_in[6];
    float* out = (float*)d_out;

    const int dyn = (int)sizeof(Smem);
    cudaFuncSetAttribute(mlp_hmma5_kernel,
                         cudaFuncAttributeMaxDynamicSharedMemorySize, dyn);

    dim3 grid(NA, NS / (128 * TILES));   // 1024 x 8
    mlp_hmma5_kernel<<<grid, 128, dyn>>>(g, W1, b1, W2, b2, W3, b3, out);
}

// round 13
// speedup vs baseline: 1.2137x; 1.2137x over previous
#include <cuda_runtime.h>
#include <cuda_fp16.h>
#include <cstdint>

#define NS 4096
#define NA 1024
#define ND 5
#define NH 64
#define TILES 4
#define PADK 72          // f16 elems per row (144B): ldmatrix bank-conflict-free

struct Smem {
    __half   w2hi[NH][PADK];     // B^T: [j_out][k_in], f16 hi
    __half   w2lo[NH][PADK];     // f16 residual
    uint32_t w1ph[4][72];        // W1ext pairs (k,k+1) as f16x2: [kpair][j]
    uint32_t w1pl[4][72];
    float    b2[NH], w3[NH];
};

__device__ __forceinline__ uint32_t smem_u32(const void* p) {
    uint32_t a;
    asm("{ .reg .u64 t; cvta.to.shared.u64 t, %1; cvt.u32.u64 %0, t; }" : "=r"(a) : "l"(p));
    return a;
}
__device__ __forceinline__ void ldsm_x2(uint32_t r[2], uint32_t addr) {
    asm volatile("ldmatrix.sync.aligned.m8n8.x2.shared.b16 {%0,%1}, [%2];"
                 : "=r"(r[0]), "=r"(r[1]) : "r"(addr));
}
__device__ __forceinline__ void mma16816(float c[4], const uint32_t a[4], const uint32_t b[2]) {
    asm volatile("mma.sync.aligned.m16n8k16.row.col.f32.f16.f16.f32 "
                 "{%0,%1,%2,%3}, {%4,%5,%6,%7}, {%8,%9}, {%0,%1,%2,%3};"
                 : "+f"(c[0]), "+f"(c[1]), "+f"(c[2]), "+f"(c[3])
                 : "r"(a[0]), "r"(a[1]), "r"(a[2]), "r"(a[3]), "r"(b[0]), "r"(b[1]));
}
__device__ __forceinline__ void mma16808(float c[4], uint32_t a0, uint32_t a1, uint32_t b0) {
    asm volatile("mma.sync.aligned.m16n8k8.row.col.f32.f16.f16.f32 "
                 "{%0,%1,%2,%3}, {%4,%5}, {%6}, {%0,%1,%2,%3};"
                 : "+f"(c[0]), "+f"(c[1]), "+f"(c[2]), "+f"(c[3])
                 : "r"(a0), "r"(a1), "r"(b0));
}
__device__ __forceinline__ void mma16808_z(float c[4], uint32_t a0, uint32_t a1, uint32_t b0) {
    asm volatile("mma.sync.aligned.m16n8k8.row.col.f32.f16.f16.f32 "
                 "{%0,%1,%2,%3}, {%4,%5}, {%6}, {%7,%7,%7,%7};"
                 : "=f"(c[0]), "=f"(c[1]), "=f"(c[2]), "=f"(c[3])
                 : "r"(a0), "r"(a1), "r"(b0), "f"(0.0f));
}

// HW tanh: single MUFU.TANH (PTX tanh.approx.f32, baseline sm_75+).
__device__ __forceinline__ float fast_tanh(float x) {
    float y;
    asm("tanh.approx.f32 %0, %1;" : "=f"(y) : "f"(x));
    return y;
}
__device__ __forceinline__ uint32_t h2u(__half2 h) { return *reinterpret_cast<uint32_t*>(&h); }

__device__ __forceinline__ void split2(float x, float y, uint32_t& hi, uint32_t& lo) {
    __half2 h = __floats2half2_rn(x, y);
    float2  f = __half22float2(h);
    hi = h2u(h);
    lo = h2u(__floats2half2_rn(x - f.x, y - f.y));
}

__global__ void __launch_bounds__(128, 3) mlp_hmma6_kernel(
    const float* __restrict__ g,
    const float* __restrict__ W1, const float* __restrict__ b1,
    const float* __restrict__ W2, const float* __restrict__ b2,
    const float* __restrict__ W3, const float* __restrict__ b3,
    float* __restrict__ out)
{
    extern __shared__ __align__(16) char smem_raw[];
    Smem* sm = reinterpret_cast<Smem*>(smem_raw);

    const int a    = blockIdx.x;
    const int tid  = threadIdx.x;
    const int w    = tid >> 5;
    const int lane = tid & 31;
    const int q    = lane & 3;
    const int r0   = lane >> 2;

    // ---- stage W2 -> transposed split-f16 tiles ----
    for (int e = tid; e < NH * NH; e += 128) {
        int kin = e >> 6, j = e & 63;
        float v = W2[(size_t)a * NH * NH + e];
        __half hi = __float2half_rn(v);
        sm->w2hi[j][kin] = hi;
        sm->w2lo[j][kin] = __float2half_rn(v - __half2float(hi));
    }
    // ---- stage W1ext pairs: rows 0..4 = W1, row 5 = b1, rows 6,7 = 0 ----
    for (int e = tid; e < 256; e += 128) {
        int kp = e >> 6, j = e & 63;
        int k0 = 2 * kp, k1 = k0 + 1;
        float x = (k0 < ND) ? W1[(size_t)a * ND * NH + k0 * NH + j] : 0.0f;
        float y = (k1 < ND) ? W1[(size_t)a * ND * NH + k1 * NH + j]
                            : ((k1 == ND) ? b1[(size_t)a * NH + j] : 0.0f);
        uint32_t hi, lo;
        split2(x, y, hi, lo);
        sm->w1ph[kp][j] = hi;
        sm->w1pl[kp][j] = lo;
    }
    if (tid < NH) {
        sm->b2[tid] = b2[(size_t)a * NH + tid];
        sm->w3[tid] = W3[(size_t)a * NH + tid];
    }
    __syncthreads();

    const float bias3 = b3[a];
    const uint32_t aBhi = smem_u32(&sm->w2hi[lane & 7][0]) + ((lane >> 3) & 1) * 16;
    const uint32_t aBlo = smem_u32(&sm->w2lo[lane & 7][0]) + ((lane >> 3) & 1) * 16;

    // ---- loop-invariant W1ext B-fragments ----
    uint32_t bw1h[8], bw1l[8];
#pragma unroll
    for (int nt = 0; nt < 8; nt++) {
        bw1h[nt] = sm->w1ph[q][nt * 8 + r0];
        bw1l[nt] = sm->w1pl[q][nt * 8 + r0];
    }

    const int swb0 = blockIdx.y * TILES * 128 + w * 32;
    const int d0   = 2 * q;

    // ---- g raw prefetch (tile 0) ----
    float grx[2][2], gry[2][2];
#pragma unroll
    for (int mt = 0; mt < 2; mt++)
#pragma unroll
        for (int rr = 0; rr < 2; rr++) {
            const size_t idx = ((size_t)(swb0 + mt * 16 + r0 + 8 * rr) * NA + a) * ND;
            grx[mt][rr] = (d0 < ND)     ? g[idx + d0]     : 0.0f;
            gry[mt][rr] = (d0 + 1 < ND) ? g[idx + d0 + 1] : 0.0f;
        }

#pragma unroll 1
    for (int t = 0; t < TILES; t++) {
        const int swb = swb0 + t * 128;

        // ---- build g A-fragments; d=5 slot carries 1.0 (bias row) ----
        uint32_t gh[2][2], gl[2][2];
#pragma unroll
        for (int mt = 0; mt < 2; mt++)
#pragma unroll
            for (int rr = 0; rr < 2; rr++) {
                float y = (d0 + 1 == ND) ? 1.0f : gry[mt][rr];
                split2(grx[mt][rr], y, gh[mt][rr], gl[mt][rr]);
            }

        // ---- prefetch next tile's g (overlaps the MMA phase) ----
        if (t + 1 < TILES) {
#pragma unroll
            for (int mt = 0; mt < 2; mt++)
#pragma unroll
                for (int rr = 0; rr < 2; rr++) {
                    const size_t idx =
                        ((size_t)(swb + 128 + mt * 16 + r0 + 8 * rr) * NA + a) * ND;
                    grx[mt][rr] = (d0 < ND)     ? g[idx + d0]     : 0.0f;
                    gry[mt][rr] = (d0 + 1 < ND) ? g[idx + d0 + 1] : 0.0f;
                }
        }

        // ---- acc init = b2 (bias folded into the GEMM accumulator) ----
        float acc[2][8][4];
#pragma unroll
        for (int nt = 0; nt < 8; nt++) {
            float2 b2v = *(const float2*)&sm->b2[nt * 8 + q * 2];
#pragma unroll
            for (int mt = 0; mt < 2; mt++) {
                acc[mt][nt][0] = b2v.x; acc[mt][nt][1] = b2v.y;
                acc[mt][nt][2] = b2v.x; acc[mt][nt][3] = b2v.y;
            }
        }

#pragma unroll
        for (int half = 0; half < 2; half++) {
            // ---- layer-1 MMA (3-term split) for nt = 4*half .. 4*half+3 ----
            float acc1[2][4][4];
#pragma unroll
            for (int ntl = 0; ntl < 4; ntl++) {
                const int nt = 4 * half + ntl;
#pragma unroll
                for (int mt = 0; mt < 2; mt++) {
                    mma16808_z(acc1[mt][ntl], gh[mt][0], gh[mt][1], bw1h[nt]);
                    mma16808 (acc1[mt][ntl], gl[mt][0], gl[mt][1], bw1h[nt]);
                    mma16808 (acc1[mt][ntl], gh[mt][0], gh[mt][1], bw1l[nt]);
                }
            }
            // ---- per k-chunk: tanh+split, then BATCHED ldsm, then MMA burst ----
#pragma unroll
            for (int ksl = 0; ksl < 2; ksl++) {
                const int ks = 2 * half + ksl;
                uint32_t ah[2][4], al[2][4];
#pragma unroll
                for (int mt = 0; mt < 2; mt++) {
                    const float* e0 = acc1[mt][2 * ksl];
                    const float* e1 = acc1[mt][2 * ksl + 1];
                    split2(fast_tanh(e0[0]), fast_tanh(e0[1]), ah[mt][0], al[mt][0]);
                    split2(fast_tanh(e0[2]), fast_tanh(e0[3]), ah[mt][1], al[mt][1]);
                    split2(fast_tanh(e1[0]), fast_tanh(e1[1]), ah[mt][2], al[mt][2]);
                    split2(fast_tanh(e1[2]), fast_tanh(e1[3]), ah[mt][3], al[mt][3]);
                }
                // batched loads: all 16 ldsm issued before any dependent MMA (MLP=16)
                uint32_t bh2[8][2], bl2[8][2];
#pragma unroll
                for (int nt = 0; nt < 8; nt++) {
                    ldsm_x2(bh2[nt], aBhi + nt * 8 * (PADK * 2) + ks * 32);
                    ldsm_x2(bl2[nt], aBlo + nt * 8 * (PADK * 2) + ks * 32);
                }
#pragma unroll
                for (int nt = 0; nt < 8; nt++) {
#pragma unroll
                    for (int mt = 0; mt < 2; mt++) {
                        mma16816(acc[mt][nt], ah[mt], bh2[nt]);
                        mma16816(acc[mt][nt], al[mt], bh2[nt]);
                        mma16816(acc[mt][nt], ah[mt], bl2[nt]);
                    }
                }
            }
        }

        // ---- epilogue: tanh, dot(W3), quad-shuffle reduce, write 4 rows ----
        float p0 = 0.f, p1 = 0.f, p2 = 0.f, p3 = 0.f;
#pragma unroll
        for (int nt = 0; nt < 8; nt++) {
            float2 w3v = *(const float2*)&sm->w3[nt * 8 + q * 2];
            p0 = fmaf(fast_tanh(acc[0][nt][0]), w3v.x, p0);
            p0 = fmaf(fast_tanh(acc[0][nt][1]), w3v.y, p0);
            p1 = fmaf(fast_tanh(acc[0][nt][2]), w3v.x, p1);
            p1 = fmaf(fast_tanh(acc[0][nt][3]), w3v.y, p1);
            p2 = fmaf(fast_tanh(acc[1][nt][0]), w3v.x, p2);
            p2 = fmaf(fast_tanh(acc[1][nt][1]), w3v.y, p2);
            p3 = fmaf(fast_tanh(acc[1][nt][2]), w3v.x, p3);
            p3 = fmaf(fast_tanh(acc[1][nt][3]), w3v.y, p3);
        }
#pragma unroll
        for (int d = 1; d <= 2; d <<= 1) {
            p0 += __shfl_xor_sync(0xFFFFFFFFu, p0, d);
            p1 += __shfl_xor_sync(0xFFFFFFFFu, p1, d);
            p2 += __shfl_xor_sync(0xFFFFFFFFu, p2, d);
            p3 += __shfl_xor_sync(0xFFFFFFFFu, p3, d);
        }
        if (q == 0) {
            const int rb = swb + r0;
            out[(size_t)(rb +  0) * NA + a] = p0 + bias3;
            out[(size_t)(rb +  8) * NA + a] = p1 + bias3;
            out[(size_t)(rb + 16) * NA + a] = p2 + bias3;
            out[(size_t)(rb + 24) * NA + a] = p3 + bias3;
        }
    }
}

extern "C" void kernel_launch(void* const* d_in, const int* in_sizes, int n_in,
                              void* d_out, int out_size) {
    const float* g  = (const float*)d_in[0];
    const float* W1 = (const float*)d_in[1];
    const float* b1 = (const float*)d_in[2];
    const float* W2 = (const float*)d_in[3];
    const float* b2 = (const float*)d_in[4];
    const float* W3 = (const float*)d_in[5];
    const float* b3 = (const float*)d_in[6];
    float* out = (float*)d_out;

    const int dyn = (int)sizeof(Smem);
    cudaFuncSetAttribute(mlp_hmma6_kernel,
                         cudaFuncAttributeMaxDynamicSharedMemorySize, dyn);

    dim3 grid(NA, NS / (128 * TILES));   // 1024 x 8
    mlp_hmma6_kernel<<<grid, 128, dyn>>>(g, W1, b1, W2, b2, W3, b3, out);
}

// round 14
// speedup vs baseline: 1.2219x; 1.0067x over previous
#include <cuda_runtime.h>
#include <cuda_fp16.h>
#include <cstdint>

#define NS 4096
#define NA 1024
#define ND 5
#define NH 64
#define TILES 8          // 64-struct tiles per CTA
#define PADK 72          // f16 elems per row (144B): ldmatrix bank-conflict-free

struct Smem {
    __half   w2hi[NH][PADK];     // B^T: [j_out][k_in], f16 hi
    __half   w2lo[NH][PADK];     // f16 residual
    uint32_t w1ph[4][72];        // W1ext pairs (k,k+1) as f16x2: [kpair][j]
    uint32_t w1pl[4][72];
    float    b2[NH], w3[NH];
};

__device__ __forceinline__ uint32_t smem_u32(const void* p) {
    uint32_t a;
    asm("{ .reg .u64 t; cvta.to.shared.u64 t, %1; cvt.u32.u64 %0, t; }" : "=r"(a) : "l"(p));
    return a;
}
__device__ __forceinline__ void ldsm_x2(uint32_t r[2], uint32_t addr) {
    asm volatile("ldmatrix.sync.aligned.m8n8.x2.shared.b16 {%0,%1}, [%2];"
                 : "=r"(r[0]), "=r"(r[1]) : "r"(addr));
}
__device__ __forceinline__ void mma16816(float c[4], const uint32_t a[4], const uint32_t b[2]) {
    asm volatile("mma.sync.aligned.m16n8k16.row.col.f32.f16.f16.f32 "
                 "{%0,%1,%2,%3}, {%4,%5,%6,%7}, {%8,%9}, {%0,%1,%2,%3};"
                 : "+f"(c[0]), "+f"(c[1]), "+f"(c[2]), "+f"(c[3])
                 : "r"(a[0]), "r"(a[1]), "r"(a[2]), "r"(a[3]), "r"(b[0]), "r"(b[1]));
}
__device__ __forceinline__ void mma16808(float c[4], uint32_t a0, uint32_t a1, uint32_t b0) {
    asm volatile("mma.sync.aligned.m16n8k8.row.col.f32.f16.f16.f32 "
                 "{%0,%1,%2,%3}, {%4,%5}, {%6}, {%0,%1,%2,%3};"
                 : "+f"(c[0]), "+f"(c[1]), "+f"(c[2]), "+f"(c[3])
                 : "r"(a0), "r"(a1), "r"(b0));
}
__device__ __forceinline__ void mma16808_z(float c[4], uint32_t a0, uint32_t a1, uint32_t b0) {
    asm volatile("mma.sync.aligned.m16n8k8.row.col.f32.f16.f16.f32 "
                 "{%0,%1,%2,%3}, {%4,%5}, {%6}, {%7,%7,%7,%7};"
                 : "=f"(c[0]), "=f"(c[1]), "=f"(c[2]), "=f"(c[3])
                 : "r"(a0), "r"(a1), "r"(b0), "f"(0.0f));
}

// HW tanh: single MUFU.TANH (PTX tanh.approx.f32, baseline sm_75+).
__device__ __forceinline__ float fast_tanh(float x) {
    float y;
    asm("tanh.approx.f32 %0, %1;" : "=f"(y) : "f"(x));
    return y;
}
__device__ __forceinline__ uint32_t h2u(__half2 h) { return *reinterpret_cast<uint32_t*>(&h); }

__device__ __forceinline__ void split2(float x, float y, uint32_t& hi, uint32_t& lo) {
    __half2 h = __floats2half2_rn(x, y);
    float2  f = __half22float2(h);
    hi = h2u(h);
    lo = h2u(__floats2half2_rn(x - f.x, y - f.y));
}

__global__ void __launch_bounds__(128, 4) mlp_hmma7_kernel(
    const float* __restrict__ g,
    const float* __restrict__ W1, const float* __restrict__ b1,
    const float* __restrict__ W2, const float* __restrict__ b2,
    const float* __restrict__ W3, const float* __restrict__ b3,
    float* __restrict__ out)
{
    extern __shared__ __align__(16) char smem_raw[];
    Smem* sm = reinterpret_cast<Smem*>(smem_raw);

    const int a    = blockIdx.x;
    const int tid  = threadIdx.x;
    const int w    = tid >> 5;
    const int lane = tid & 31;
    const int q    = lane & 3;
    const int r0   = lane >> 2;

    // ---- stage W2 -> transposed split-f16 tiles ----
    for (int e = tid; e < NH * NH; e += 128) {
        int kin = e >> 6, j = e & 63;
        float v = W2[(size_t)a * NH * NH + e];
        __half hi = __float2half_rn(v);
        sm->w2hi[j][kin] = hi;
        sm->w2lo[j][kin] = __float2half_rn(v - __half2float(hi));
    }
    // ---- stage W1ext pairs: rows 0..4 = W1, row 5 = b1, rows 6,7 = 0 ----
    for (int e = tid; e < 256; e += 128) {
        int kp = e >> 6, j = e & 63;
        int k0 = 2 * kp, k1 = k0 + 1;
        float x = (k0 < ND) ? W1[(size_t)a * ND * NH + k0 * NH + j] : 0.0f;
        float y = (k1 < ND) ? W1[(size_t)a * ND * NH + k1 * NH + j]
                            : ((k1 == ND) ? b1[(size_t)a * NH + j] : 0.0f);
        uint32_t hi, lo;
        split2(x, y, hi, lo);
        sm->w1ph[kp][j] = hi;
        sm->w1pl[kp][j] = lo;
    }
    if (tid < NH) {
        sm->b2[tid] = b2[(size_t)a * NH + tid];
        sm->w3[tid] = W3[(size_t)a * NH + tid];
    }
    __syncthreads();

    const float bias3 = b3[a];
    const uint32_t aBhi = smem_u32(&sm->w2hi[lane & 7][0]) + ((lane >> 3) & 1) * 16;
    const uint32_t aBlo = smem_u32(&sm->w2lo[lane & 7][0]) + ((lane >> 3) & 1) * 16;

    // ---- loop-invariant W1ext B-fragments ----
    uint32_t bw1h[8], bw1l[8];
#pragma unroll
    for (int nt = 0; nt < 8; nt++) {
        bw1h[nt] = sm->w1ph[q][nt * 8 + r0];
        bw1l[nt] = sm->w1pl[q][nt * 8 + r0];
    }

    const int swb0 = blockIdx.y * TILES * 64 + w * 16;   // warp's 16-row slice
    const int d0   = 2 * q;

    // ---- g raw prefetch (tile 0): one row per rr in {0,1} ----
    float grx[2], gry[2];
#pragma unroll
    for (int rr = 0; rr < 2; rr++) {
        const size_t idx = ((size_t)(swb0 + r0 + 8 * rr) * NA + a) * ND;
        grx[rr] = (d0 < ND)     ? g[idx + d0]     : 0.0f;
        gry[rr] = (d0 + 1 < ND) ? g[idx + d0 + 1] : 0.0f;
    }

#pragma unroll 1
    for (int t = 0; t < TILES; t++) {
        const int swb = swb0 + t * 64;

        // ---- build g A-fragments; d=5 slot carries 1.0 (bias row) ----
        uint32_t gh[2], gl[2];
#pragma unroll
        for (int rr = 0; rr < 2; rr++) {
            float y = (d0 + 1 == ND) ? 1.0f : gry[rr];
            split2(grx[rr], y, gh[rr], gl[rr]);
        }

        // ---- prefetch next tile's g ----
        if (t + 1 < TILES) {
#pragma unroll
            for (int rr = 0; rr < 2; rr++) {
                const size_t idx = ((size_t)(swb + 64 + r0 + 8 * rr) * NA + a) * ND;
                grx[rr] = (d0 < ND)     ? g[idx + d0]     : 0.0f;
                gry[rr] = (d0 + 1 < ND) ? g[idx + d0 + 1] : 0.0f;
            }
        }

        // ---- acc init = b2 (bias folded) ----
        float acc[8][4];
#pragma unroll
        for (int nt = 0; nt < 8; nt++) {
            float2 b2v = *(const float2*)&sm->b2[nt * 8 + q * 2];
            acc[nt][0] = b2v.x; acc[nt][1] = b2v.y;
            acc[nt][2] = b2v.x; acc[nt][3] = b2v.y;
        }

#pragma unroll
        for (int half = 0; half < 2; half++) {
            // ---- layer-1 MMA (3-term split) for nt = 4*half .. 4*half+3 ----
            float acc1[4][4];
#pragma unroll
            for (int ntl = 0; ntl < 4; ntl++) {
                const int nt = 4 * half + ntl;
                mma16808_z(acc1[ntl], gh[0], gh[1], bw1h[nt]);
                mma16808 (acc1[ntl], gl[0], gl[1], bw1h[nt]);
                mma16808 (acc1[ntl], gh[0], gh[1], bw1l[nt]);
            }
            // ---- per k-chunk: tanh+split -> layer-2 MMAs ----
#pragma unroll
            for (int ksl = 0; ksl < 2; ksl++) {
                const int ks = 2 * half + ksl;
                uint32_t ah[4], al[4];
                {
                    const float* e0 = acc1[2 * ksl];
                    const float* e1 = acc1[2 * ksl + 1];
                    split2(fast_tanh(e0[0]), fast_tanh(e0[1]), ah[0], al[0]);
                    split2(fast_tanh(e0[2]), fast_tanh(e0[3]), ah[1], al[1]);
                    split2(fast_tanh(e1[0]), fast_tanh(e1[1]), ah[2], al[2]);
                    split2(fast_tanh(e1[2]), fast_tanh(e1[3]), ah[3], al[3]);
                }
#pragma unroll
                for (int nt = 0; nt < 8; nt++) {
                    uint32_t bh2[2], bl2[2];
                    ldsm_x2(bh2, aBhi + nt * 8 * (PADK * 2) + ks * 32);
                    ldsm_x2(bl2, aBlo + nt * 8 * (PADK * 2) + ks * 32);
                    mma16816(acc[nt], ah, bh2);
                    mma16816(acc[nt], al, bh2);
                    mma16816(acc[nt], ah, bl2);
                }
            }
        }

        // ---- epilogue: tanh, dot(W3), quad-shuffle reduce, write 2 rows ----
        float p0 = 0.f, p1 = 0.f;
#pragma unroll
        for (int nt = 0; nt < 8; nt++) {
            float2 w3v = *(const float2*)&sm->w3[nt * 8 + q * 2];
            p0 = fmaf(fast_tanh(acc[nt][0]), w3v.x, p0);
            p0 = fmaf(fast_tanh(acc[nt][1]), w3v.y, p0);
            p1 = fmaf(fast_tanh(acc[nt][2]), w3v.x, p1);
            p1 = fmaf(fast_tanh(acc[nt][3]), w3v.y, p1);
        }
#pragma unroll
        for (int d = 1; d <= 2; d <<= 1) {
            p0 += __shfl_xor_sync(0xFFFFFFFFu, p0, d);
            p1 += __shfl_xor_sync(0xFFFFFFFFu, p1, d);
        }
        if (q == 0) {
            const int rb = swb + r0;
            out[(size_t)(rb + 0) * NA + a] = p0 + bias3;
            out[(size_t)(rb + 8) * NA + a] = p1 + bias3;
        }
    }
}

extern "C" void kernel_launch(void* const* d_in, const int* in_sizes, int n_in,
                              void* d_out, int out_size) {
    const float* g  = (const float*)d_in[0];
    const float* W1 = (const float*)d_in[1];
    const float* b1 = (const float*)d_in[2];
    const float* W2 = (const float*)d_in[3];
    const float* b2 = (const float*)d_in[4];
    const float* W3 = (const float*)d_in[5];
    const float* b3 = (const float*)d_in[6];
    float* out = (float*)d_out;

    const int dyn = (int)sizeof(Smem);
    cudaFuncSetAttribute(mlp_hmma7_kernel,
                         cudaFuncAttributeMaxDynamicSharedMemorySize, dyn);

    dim3 grid(NA, NS / (64 * TILES));   // 1024 x 8
    mlp_hmma7_kernel<<<grid, 128, dyn>>>(g, W1, b1, W2, b2, W3, b3, out);
}

// round 16
// speedup vs baseline: 1.4987x; 1.2266x over previous
#include <cuda_runtime.h>
#include <cuda_fp16.h>
#include <cstdint>

#define NS 4096
#define NA 1024
#define ND 5
#define NH 64
#define TILES 4
#define PADK 72          // f16 elems per row (144B): ldmatrix bank-conflict-free

struct Smem {
    __half   w2hi[NH][PADK];     // B^T: [j_out][k_in], f16 (layer-2 residual dropped)
    uint32_t w1ph[4][72];        // W1ext pairs (k,k+1) as f16x2: [kpair][j]
    uint32_t w1pl[4][72];        // layer-1 keeps full 3-term split
    float    b2[NH], w3[NH];
};

__device__ __forceinline__ uint32_t smem_u32(const void* p) {
    uint32_t a;
    asm("{ .reg .u64 t; cvta.to.shared.u64 t, %1; cvt.u32.u64 %0, t; }" : "=r"(a) : "l"(p));
    return a;
}
__device__ __forceinline__ void ldsm_x2(uint32_t r[2], uint32_t addr) {
    asm volatile("ldmatrix.sync.aligned.m8n8.x2.shared.b16 {%0,%1}, [%2];"
                 : "=r"(r[0]), "=r"(r[1]) : "r"(addr));
}
__device__ __forceinline__ void mma16816(float c[4], const uint32_t a[4], const uint32_t b[2]) {
    asm volatile("mma.sync.aligned.m16n8k16.row.col.f32.f16.f16.f32 "
                 "{%0,%1,%2,%3}, {%4,%5,%6,%7}, {%8,%9}, {%0,%1,%2,%3};"
                 : "+f"(c[0]), "+f"(c[1]), "+f"(c[2]), "+f"(c[3])
                 : "r"(a[0]), "r"(a[1]), "r"(a[2]), "r"(a[3]), "r"(b[0]), "r"(b[1]));
}
__device__ __forceinline__ void mma16808(float c[4], uint32_t a0, uint32_t a1, uint32_t b0) {
    asm volatile("mma.sync.aligned.m16n8k8.row.col.f32.f16.f16.f32 "
                 "{%0,%1,%2,%3}, {%4,%5}, {%6}, {%0,%1,%2,%3};"
                 : "+f"(c[0]), "+f"(c[1]), "+f"(c[2]), "+f"(c[3])
                 : "r"(a0), "r"(a1), "r"(b0));
}
__device__ __forceinline__ void mma16808_z(float c[4], uint32_t a0, uint32_t a1, uint32_t b0) {
    asm volatile("mma.sync.aligned.m16n8k8.row.col.f32.f16.f16.f32 "
                 "{%0,%1,%2,%3}, {%4,%5}, {%6}, {%7,%7,%7,%7};"
                 : "=f"(c[0]), "=f"(c[1]), "=f"(c[2]), "=f"(c[3])
                 : "r"(a0), "r"(a1), "r"(b0), "f"(0.0f));
}

// HW tanh: single MUFU.TANH (PTX tanh.approx.f32, baseline sm_75+).
__device__ __forceinline__ float fast_tanh(float x) {
    float y;
    asm("tanh.approx.f32 %0, %1;" : "=f"(y) : "f"(x));
    return y;
}
__device__ __forceinline__ uint32_t h2u(__half2 h) { return *reinterpret_cast<uint32_t*>(&h); }

__device__ __forceinline__ void split2(float x, float y, uint32_t& hi, uint32_t& lo) {
    __half2 h = __floats2half2_rn(x, y);
    float2  f = __half22float2(h);
    hi = h2u(h);
    lo = h2u(__floats2half2_rn(x - f.x, y - f.y));
}

__global__ void __launch_bounds__(128, 3) mlp_hmma8_kernel(
    const float* __restrict__ g,
    const float* __restrict__ W1, const float* __restrict__ b1,
    const float* __restrict__ W2, const float* __restrict__ b2,
    const float* __restrict__ W3, const float* __restrict__ b3,
    float* __restrict__ out)
{
    extern __shared__ __align__(16) char smem_raw[];
    Smem* sm = reinterpret_cast<Smem*>(smem_raw);

    const int a    = blockIdx.x;
    const int tid  = threadIdx.x;
    const int w    = tid >> 5;
    const int lane = tid & 31;
    const int q    = lane & 3;
    const int r0   = lane >> 2;

    // ---- stage W2 (f16 hi only), transposed: B^T[j][k] ----
    for (int e = tid; e < NH * NH; e += 128) {
        int kin = e >> 6, j = e & 63;
        sm->w2hi[j][kin] = __float2half_rn(W2[(size_t)a * NH * NH + e]);
    }
    // ---- stage W1ext pairs: rows 0..4 = W1, row 5 = b1, rows 6,7 = 0 ----
    for (int e = tid; e < 256; e += 128) {
        int kp = e >> 6, j = e & 63;
        int k0 = 2 * kp, k1 = k0 + 1;
        float x = (k0 < ND) ? W1[(size_t)a * ND * NH + k0 * NH + j] : 0.0f;
        float y = (k1 < ND) ? W1[(size_t)a * ND * NH + k1 * NH + j]
                            : ((k1 == ND) ? b1[(size_t)a * NH + j] : 0.0f);
        uint32_t hi, lo;
        split2(x, y, hi, lo);
        sm->w1ph[kp][j] = hi;
        sm->w1pl[kp][j] = lo;
    }
    if (tid < NH) {
        sm->b2[tid] = b2[(size_t)a * NH + tid];
        sm->w3[tid] = W3[(size_t)a * NH + tid];
    }
    __syncthreads();

    const float bias3 = b3[a];
    const uint32_t aBhi = smem_u32(&sm->w2hi[lane & 7][0]) + ((lane >> 3) & 1) * 16;

    // ---- loop-invariant W1ext B-fragments ----
    uint32_t bw1h[8], bw1l[8];
#pragma unroll
    for (int nt = 0; nt < 8; nt++) {
        bw1h[nt] = sm->w1ph[q][nt * 8 + r0];
        bw1l[nt] = sm->w1pl[q][nt * 8 + r0];
    }

    const int swb0 = blockIdx.y * TILES * 128 + w * 32;
    const int d0   = 2 * q;

    // ---- g raw prefetch (tile 0) ----
    float grx[2][2], gry[2][2];
#pragma unroll
    for (int mt = 0; mt < 2; mt++)
#pragma unroll
        for (int rr = 0; rr < 2; rr++) {
            const size_t idx = ((size_t)(swb0 + mt * 16 + r0 + 8 * rr) * NA + a) * ND;
            grx[mt][rr] = (d0 < ND)     ? g[idx + d0]     : 0.0f;
            gry[mt][rr] = (d0 + 1 < ND) ? g[idx + d0 + 1] : 0.0f;
        }

#pragma unroll 1
    for (int t = 0; t < TILES; t++) {
        const int swb = swb0 + t * 128;

        // ---- build g A-fragments; d=5 slot carries 1.0 (bias row) ----
        uint32_t gh[2][2], gl[2][2];
#pragma unroll
        for (int mt = 0; mt < 2; mt++)
#pragma unroll
            for (int rr = 0; rr < 2; rr++) {
                float y = (d0 + 1 == ND) ? 1.0f : gry[mt][rr];
                split2(grx[mt][rr], y, gh[mt][rr], gl[mt][rr]);
            }

        // ---- prefetch next tile's g (overlaps the MMA phase) ----
        if (t + 1 < TILES) {
#pragma unroll
            for (int mt = 0; mt < 2; mt++)
#pragma unroll
                for (int rr = 0; rr < 2; rr++) {
                    const size_t idx =
                        ((size_t)(swb + 128 + mt * 16 + r0 + 8 * rr) * NA + a) * ND;
                    grx[mt][rr] = (d0 < ND)     ? g[idx + d0]     : 0.0f;
                    gry[mt][rr] = (d0 + 1 < ND) ? g[idx + d0 + 1] : 0.0f;
                }
        }

        // ---- acc init = b2 (bias folded into the GEMM accumulator) ----
        float acc[2][8][4];
#pragma unroll
        for (int nt = 0; nt < 8; nt++) {
            float2 b2v = *(const float2*)&sm->b2[nt * 8 + q * 2];
#pragma unroll
            for (int mt = 0; mt < 2; mt++) {
                acc[mt][nt][0] = b2v.x; acc[mt][nt][1] = b2v.y;
                acc[mt][nt][2] = b2v.x; acc[mt][nt][3] = b2v.y;
            }
        }

#pragma unroll
        for (int half = 0; half < 2; half++) {
            // ---- layer-1 MMA (3-term split) for nt = 4*half .. 4*half+3 ----
            float acc1[2][4][4];
#pragma unroll
            for (int ntl = 0; ntl < 4; ntl++) {
                const int nt = 4 * half + ntl;
#pragma unroll
                for (int mt = 0; mt < 2; mt++) {
                    mma16808_z(acc1[mt][ntl], gh[mt][0], gh[mt][1], bw1h[nt]);
                    mma16808 (acc1[mt][ntl], gl[mt][0], gl[mt][1], bw1h[nt]);
                    mma16808 (acc1[mt][ntl], gh[mt][0], gh[mt][1], bw1l[nt]);
                }
            }
            // ---- per k-chunk: tanh+split, batched ldsm, 2-term MMA burst ----
#pragma unroll
            for (int ksl = 0; ksl < 2; ksl++) {
                const int ks = 2 * half + ksl;
                uint32_t ah[2][4], al[2][4];
#pragma unroll
                for (int mt = 0; mt < 2; mt++) {
                    const float* e0 = acc1[mt][2 * ksl];
                    const float* e1 = acc1[mt][2 * ksl + 1];
                    split2(fast_tanh(e0[0]), fast_tanh(e0[1]), ah[mt][0], al[mt][0]);
                    split2(fast_tanh(e0[2]), fast_tanh(e0[3]), ah[mt][1], al[mt][1]);
                    split2(fast_tanh(e1[0]), fast_tanh(e1[1]), ah[mt][2], al[mt][2]);
                    split2(fast_tanh(e1[2]), fast_tanh(e1[3]), ah[mt][3], al[mt][3]);
                }
                // batched loads: all 8 ldsm issued before any dependent MMA
                uint32_t bh2[8][2];
#pragma unroll
                for (int nt = 0; nt < 8; nt++)
                    ldsm_x2(bh2[nt], aBhi + nt * 8 * (PADK * 2) + ks * 32);
#pragma unroll
                for (int nt = 0; nt < 8; nt++) {
#pragma unroll
                    for (int mt = 0; mt < 2; mt++) {
                        mma16816(acc[mt][nt], ah[mt], bh2[nt]);
                        mma16816(acc[mt][nt], al[mt], bh2[nt]);
                    }
                }
            }
        }

        // ---- epilogue: tanh, dot(W3), quad-shuffle reduce, write 4 rows ----
        float p0 = 0.f, p1 = 0.f, p2 = 0.f, p3 = 0.f;
#pragma unroll
        for (int nt = 0; nt < 8; nt++) {
            float2 w3v = *(const float2*)&sm->w3[nt * 8 + q * 2];
            p0 = fmaf(fast_tanh(acc[0][nt][0]), w3v.x, p0);
            p0 = fmaf(fast_tanh(acc[0][nt][1]), w3v.y, p0);
            p1 = fmaf(fast_tanh(acc[0][nt][2]), w3v.x, p1);
            p1 = fmaf(fast_tanh(acc[0][nt][3]), w3v.y, p1);
            p2 = fmaf(fast_tanh(acc[1][nt][0]), w3v.x, p2);
            p2 = fmaf(fast_tanh(acc[1][nt][1]), w3v.y, p2);
            p3 = fmaf(fast_tanh(acc[1][nt][2]), w3v.x, p3);
            p3 = fmaf(fast_tanh(acc[1][nt][3]), w3v.y, p3);
        }
#pragma unroll
        for (int d = 1; d <= 2; d <<= 1) {
            p0 += __shfl_xor_sync(0xFFFFFFFFu, p0, d);
            p1 += __shfl_xor_sync(0xFFFFFFFFu, p1, d);
            p2 += __shfl_xor_sync(0xFFFFFFFFu, p2, d);
            p3 += __shfl_xor_sync(0xFFFFFFFFu, p3, d);
        }
        if (q == 0) {
            const int rb = swb + r0;
            out[(size_t)(rb +  0) * NA + a] = p0 + bias3;
            out[(size_t)(rb +  8) * NA + a] = p1 + bias3;
            out[(size_t)(rb + 16) * NA + a] = p2 + bias3;
            out[(size_t)(rb + 24) * NA + a] = p3 + bias3;
        }
    }
}

extern "C" void kernel_launch(void* const* d_in, const int* in_sizes, int n_in,
                              void* d_out, int out_size) {
    const float* g  = (const float*)d_in[0];
    const float* W1 = (const float*)d_in[1];
    const float* b1 = (const float*)d_in[2];
    const float* W2 = (const float*)d_in[3];
    const float* b2 = (const float*)d_in[4];
    const float* W3 = (const float*)d_in[5];
    const float* b3 = (const float*)d_in[6];
    float* out = (float*)d_out;

    const int dyn = (int)sizeof(Smem);
    cudaFuncSetAttribute(mlp_hmma8_kernel,
                         cudaFuncAttributeMaxDynamicSharedMemorySize, dyn);

    dim3 grid(NA, NS / (128 * TILES));   // 1024 x 8
    mlp_hmma8_kernel<<<grid, 128, dyn>>>(g, W1, b1, W2, b2, W3, b3, out);
}